// round 12
// baseline (speedup 1.0000x reference)
#include <cuda_runtime.h>
#include <cuda_fp16.h>
#include <cstdint>
#include <math.h>

#define BATCH 256
#define TLEN  512
#define COUT  320
#define CPAD  320
#define NSUBJ 4
#define EPSBN 1e-5f

// ================= scratch (no allocations allowed) =================
__device__ float g_bufA[(size_t)BATCH * COUT * TLEN];
__device__ float g_bufB[(size_t)BATCH * COUT * TLEN];
__device__ __half g_hi[(size_t)BATCH * TLEN * CPAD];   // [b][t][c] fp16 hi split
__device__ __half g_lo[(size_t)BATCH * TLEN * CPAD];   // [b][t][c] fp16 lo split
__device__ __half g_wfmt[3 * 6 * 320 * 320];           // [layer][(ko*2+sp)][co][ci]
__device__ float g_part1[8 * BATCH * COUT];            // [tt][b][co]
__device__ float g_part2[8 * BATCH * COUT];
__device__ float g_scale[NSUBJ * COUT];
__device__ float g_shift[NSUBJ * COUT];

// ================= mma / ldmatrix / cp.async helpers =================
__device__ __forceinline__ uint32_t smem_addr(const void* p) {
    return (uint32_t)__cvta_generic_to_shared(p);
}
__device__ __forceinline__ void ldsm_x4(uint32_t* r, uint32_t addr) {
    asm volatile("ldmatrix.sync.aligned.m8n8.x4.shared.b16 {%0,%1,%2,%3}, [%4];"
                 : "=r"(r[0]), "=r"(r[1]), "=r"(r[2]), "=r"(r[3]) : "r"(addr));
}
__device__ __forceinline__ void ldsm_x2(uint32_t* r, uint32_t addr) {
    asm volatile("ldmatrix.sync.aligned.m8n8.x2.shared.b16 {%0,%1}, [%2];"
                 : "=r"(r[0]), "=r"(r[1]) : "r"(addr));
}
// f32-accum fp16 mma (main product)
__device__ __forceinline__ void mma_f32(float* c, const uint32_t* a, const uint32_t* b) {
    asm volatile("mma.sync.aligned.m16n8k16.row.col.f32.f16.f16.f32 "
                 "{%0,%1,%2,%3}, {%4,%5,%6,%7}, {%8,%9}, {%0,%1,%2,%3};"
                 : "+f"(c[0]), "+f"(c[1]), "+f"(c[2]), "+f"(c[3])
                 : "r"(a[0]), "r"(a[1]), "r"(a[2]), "r"(a[3]), "r"(b[0]), "r"(b[1]));
}
// f16-accum fp16 mma (correction products, 2x rate)
__device__ __forceinline__ void mma_f16(uint32_t* c, const uint32_t* a, const uint32_t* b) {
    asm volatile("mma.sync.aligned.m16n8k16.row.col.f16.f16.f16.f16 "
                 "{%0,%1}, {%2,%3,%4,%5}, {%6,%7}, {%0,%1};"
                 : "+r"(c[0]), "+r"(c[1])
                 : "r"(a[0]), "r"(a[1]), "r"(a[2]), "r"(a[3]), "r"(b[0]), "r"(b[1]));
}
__device__ __forceinline__ void cp16(uint32_t dst, const void* src) {
    asm volatile("cp.async.cg.shared.global [%0], [%1], 16;" :: "r"(dst), "l"(src));
}
__device__ __forceinline__ void cp16z(uint32_t dst, const void* src, int sz) {
    asm volatile("cp.async.cg.shared.global [%0], [%1], 16, %2;" :: "r"(dst), "l"(src), "r"(sz));
}
#define CP_COMMIT() asm volatile("cp.async.commit_group;")
#define CP_WAIT(n)  asm volatile("cp.async.wait_group %0;" :: "n"(n))

// swizzled 16B-half selector: conflict-free ldsm for 32B rows
#define SWH(r, h) ((h) ^ ((r) & 1) ^ (((r) >> 2) & 1))

// ================= conv via warp MMA =================
// CTA tile: 128 t x 64 co; 8 warps (4 t-warps x 2 co-warps); warp tile 32t x 32co.
// A = X^T smem [row=t][16 ci] (tap = +ko rows), B = W smem [co][16 ci].
// Products: f32acc hi*Whi; f16acc (hi*Wlo + lo*Whi)  [lo*lo dropped, ~2^-22].
#define XROWS   132
#define XSLAB   (XROWS * 32)             // 4224 B per split slab
#define XSTG    (2 * XSLAB)              // 8448 B per stage
#define WTILE   (64 * 32)                // 2048 B per (ko,sp) tile
#define WSTG    (6 * WTILE)              // 12288 B per stage
#define WBASE   (2 * XSTG)               // 16896
#define CONV_SMEM (WBASE + 2 * WSTG)     // 41472 B

__global__ __launch_bounds__(256, 2)
void conv_mma_kernel(const __half* __restrict__ xhi,
                     const __half* __restrict__ xlo,
                     const __half* __restrict__ wf,
                     const float* __restrict__ bias,
                     const float* __restrict__ resid,
                     float* __restrict__ out,
                     int nch)
{
    extern __shared__ char smem[];
    const uint32_t sb = smem_addr(smem);

    const int tid  = threadIdx.x;
    const int wid  = tid >> 5;
    const int lane = tid & 31;
    const int co_blk = blockIdx.x * 64;
    const int t0     = blockIdx.y * 128;
    const int b      = blockIdx.z;

    const int warp_t0  = (wid >> 1) * 32;      // 0,32,64,96
    const int warp_co0 = (wid & 1) * 32;       // 0,32

    float    acc[2][4][4];
    uint32_t cacc[2][4][2];
    #pragma unroll
    for (int m = 0; m < 2; m++)
        #pragma unroll
        for (int n = 0; n < 4; n++) {
            #pragma unroll
            for (int k = 0; k < 4; k++) acc[m][n][k] = 0.f;
            cacc[m][n][0] = 0u; cacc[m][n][1] = 0u;
        }

    const int a_row = lane & 15, a_h = lane >> 4;
    const int b_row = lane & 7,  b_h = (lane >> 3) & 1;

    auto load_chunk = [&](int ch, int st) {
        const int c0 = ch * 16;
        // X: 2 splits x 130 rows x 2 halves
        for (int idx = tid; idx < 520; idx += 256) {
            const int sp  = idx / 260;
            const int r2  = idx - sp * 260;
            const int row = r2 >> 1, h = r2 & 1;
            const int t   = t0 - 1 + row;
            const int tc  = t < 0 ? 0 : (t > TLEN - 1 ? TLEN - 1 : t);
            const __half* src = (sp ? xlo : xhi) +
                ((size_t)b * TLEN + tc) * CPAD + c0 + h * 8;
            const uint32_t dst = sb + st * XSTG + sp * XSLAB + row * 32 + SWH(row, h) * 16;
            cp16z(dst, src, (t >= 0 && t < TLEN) ? 16 : 0);
        }
        // W: 6 tiles x 64 co x 2 halves
        for (int idx = tid; idx < 768; idx += 256) {
            const int tile = idx >> 7;
            const int r    = idx & 127;
            const int co   = r >> 1, h = r & 1;
            const __half* src = wf + ((size_t)tile * 320 + co_blk + co) * 320 + c0 + h * 8;
            const uint32_t dst = sb + WBASE + st * WSTG + tile * WTILE + co * 32 + SWH(co, h) * 16;
            cp16(dst, src);
        }
        CP_COMMIT();
    };

    load_chunk(0, 0);

    for (int ch = 0; ch < nch; ch++) {
        const int st = ch & 1;
        if (ch + 1 < nch) { load_chunk(ch + 1, st ^ 1); CP_WAIT(1); }
        else              { CP_WAIT(0); }
        __syncthreads();

        const uint32_t xhi_b = sb + st * XSTG;
        const uint32_t xlo_b = xhi_b + XSLAB;
        const uint32_t wb    = sb + WBASE + st * WSTG;

        #pragma unroll
        for (int ko = 0; ko < 3; ko++) {
            uint32_t bh[4][2], bl[4][2];
            #pragma unroll
            for (int n = 0; n < 4; n++) {
                const int wr = warp_co0 + n * 8 + b_row;
                const uint32_t woff = (uint32_t)(wr * 32 + SWH(wr, b_h) * 16);
                ldsm_x2(bh[n], wb + (ko * 2 + 0) * WTILE + woff);
                ldsm_x2(bl[n], wb + (ko * 2 + 1) * WTILE + woff);
            }
            uint32_t a[2][4];
            #pragma unroll
            for (int m = 0; m < 2; m++) {
                const int xr = warp_t0 + m * 16 + ko + a_row;
                ldsm_x4(a[m], xhi_b + (uint32_t)(xr * 32 + SWH(xr, a_h) * 16));
            }
            // main product: f32 accum
            #pragma unroll
            for (int m = 0; m < 2; m++)
                #pragma unroll
                for (int n = 0; n < 4; n++) mma_f32(acc[m][n], a[m], bh[n]);
            // correction 1: hi * Wlo, f16 accum (2x rate)
            #pragma unroll
            for (int m = 0; m < 2; m++)
                #pragma unroll
                for (int n = 0; n < 4; n++) mma_f16(cacc[m][n], a[m], bl[n]);
            // correction 2: lo * Whi, f16 accum
            #pragma unroll
            for (int m = 0; m < 2; m++) {
                const int xr = warp_t0 + m * 16 + ko + a_row;
                ldsm_x4(a[m], xlo_b + (uint32_t)(xr * 32 + SWH(xr, a_h) * 16));
            }
            #pragma unroll
            for (int m = 0; m < 2; m++)
                #pragma unroll
                for (int n = 0; n < 4; n++) mma_f16(cacc[m][n], a[m], bh[n]);
        }
        __syncthreads();
    }

    // ---- epilogue: two 64-t halves via smem transpose; fused BN partial stats ----
    float* sO = (float*)smem;                   // [64 co][68 t] = 17408 B
    #pragma unroll
    for (int th = 0; th < 2; th++) {
        if ((warp_t0 >> 6) == th) {
            const int tb2 = warp_t0 & 63;       // 0 or 32
            const int t_l = lane >> 2;
            #pragma unroll
            for (int n = 0; n < 4; n++) {
                const int co_l = warp_co0 + n * 8 + ((lane & 3) << 1);
                #pragma unroll
                for (int m = 0; m < 2; m++) {
                    const int t = tb2 + m * 16 + t_l;
                    const __half2 h0 = *reinterpret_cast<const __half2*>(&cacc[m][n][0]);
                    const __half2 h1 = *reinterpret_cast<const __half2*>(&cacc[m][n][1]);
                    sO[co_l * 68 + t]           = acc[m][n][0] + __low2float(h0);
                    sO[(co_l + 1) * 68 + t]     = acc[m][n][1] + __high2float(h0);
                    sO[co_l * 68 + t + 8]       = acc[m][n][2] + __low2float(h1);
                    sO[(co_l + 1) * 68 + t + 8] = acc[m][n][3] + __high2float(h1);
                }
            }
        }
        __syncthreads();

        const int tt = blockIdx.y * 2 + th;
        for (int idx = tid; idx < 64 * 16; idx += 256) {
            const int co = idx >> 4, t4 = idx & 15;
            float4 v = *(const float4*)&sO[co * 68 + t4 * 4];
            const float bv = bias[co_blk + co];
            v.x += bv; v.y += bv; v.z += bv; v.w += bv;
            const size_t adr = ((size_t)b * COUT + co_blk + co) * TLEN + t0 + th * 64 + t4 * 4;
            if (resid) {
                const float4 r = *(const float4*)&resid[adr];
                v.x += r.x; v.y += r.y; v.z += r.z; v.w += r.w;
            }
            *(float4*)&out[adr] = v;
            float s = v.x + v.y + v.z + v.w;
            float q = v.x * v.x + v.y * v.y + v.z * v.z + v.w * v.w;
            #pragma unroll
            for (int o = 8; o > 0; o >>= 1) {
                s += __shfl_down_sync(0xffffffffu, s, o, 16);
                q += __shfl_down_sync(0xffffffffu, q, o, 16);
            }
            if ((lane & 15) == 0) {
                const size_t pa = ((size_t)tt * BATCH + b) * COUT + co_blk + co;
                g_part1[pa] = s;
                g_part2[pa] = q;
            }
        }
        __syncthreads();
    }
}

// ================= weight reformat: [(ko*2+sp)][co320][ci320] fp16 =================
__global__ void wfmt_kernel(const float* __restrict__ W, int Cin, int layer)
{
    const int idx = blockIdx.x * blockDim.x + threadIdx.x;
    if (idx >= 6 * 320 * 320) return;
    const int ci = idx % 320;
    const int co = (idx / 320) % 320;
    const int ts = idx / (320 * 320);
    const int ko = ts >> 1, sp = ts & 1;
    float v = 0.f;
    if (ci < Cin) v = W[((size_t)co * Cin + ci) * 3 + ko];
    const __half h = __float2half(v);
    g_wfmt[(size_t)layer * 6 * 320 * 320 + idx] =
        (sp == 0) ? h : __float2half(v - __half2float(h));
}

// ================= input convert: X fp32 [b][Cin][512] -> hi/lo [b][t][320] =================
__global__ void convert_x_tr_kernel(const float* __restrict__ x, int Cin)
{
    __shared__ __half sh[128][33];
    __shared__ __half sl[128][33];
    const int tid = threadIdx.x;
    const int b   = blockIdx.y;
    const int c0  = blockIdx.x * 32;

    for (int ts = 0; ts < TLEN; ts += 128) {
        for (int idx = tid; idx < 1024; idx += 256) {
            const int ci = idx >> 5, t4 = idx & 31;
            const int c = c0 + ci;
            float4 v = make_float4(0.f, 0.f, 0.f, 0.f);
            if (c < Cin) v = *(const float4*)&x[((size_t)b * Cin + c) * TLEN + ts + t4 * 4];
            const float f[4] = {v.x, v.y, v.z, v.w};
            #pragma unroll
            for (int j = 0; j < 4; j++) {
                const __half h = __float2half(f[j]);
                sh[t4 * 4 + j][ci] = h;
                sl[t4 * 4 + j][ci] = __float2half(f[j] - __half2float(h));
            }
        }
        __syncthreads();
        for (int idx = tid; idx < 1024; idx += 256) {
            const int arr = idx >> 9;
            const int rem = idx & 511;
            const int r = rem >> 2, q = rem & 3;
            const __half* src = arr ? &sl[r][q * 8] : &sh[r][q * 8];
            uint16_t tmp[8];
            #pragma unroll
            for (int j = 0; j < 8; j++) tmp[j] = ((const uint16_t*)src)[j];
            __half* dst = (arr ? g_lo : g_hi) + ((size_t)b * TLEN + ts + r) * CPAD + c0 + q * 8;
            *(uint4*)dst = *(const uint4*)tmp;
        }
        __syncthreads();
    }
}

// ================= BN stats reduce: deterministic over [tt][b] =================
__global__ void stats_reduce_g(const int* __restrict__ subj,
                               const float* __restrict__ gamma, const float* __restrict__ beta)
{
    const int idx = blockIdx.x * blockDim.x + threadIdx.x;
    if (idx >= NSUBJ * COUT) return;
    const int s = idx / COUT;
    const int c = idx - s * COUT;
    float sum = 0.f, sq = 0.f;
    int nb = 0;
    for (int b = 0; b < BATCH; b++) {
        if (subj[b] == s) {
            nb++;
            #pragma unroll
            for (int tt = 0; tt < 8; tt++) {
                const size_t pa = ((size_t)tt * BATCH + b) * COUT + c;
                sum += g_part1[pa];
                sq  += g_part2[pa];
            }
        }
    }
    const float cnt  = fmaxf((float)nb * (float)TLEN, 1.0f);
    const float mean = sum / cnt;
    const float var  = sq / cnt - mean * mean;
    const float sc   = gamma[idx] * rsqrtf(var + EPSBN);
    g_scale[idx] = sc;
    g_shift[idx] = beta[idx] - mean * sc;
}

// ====== BN apply + exact GELU (in place) + transposed hi/lo emit ======
__device__ __forceinline__ float gelu_exact(float y) {
    return 0.5f * y * (1.0f + erff(y * 0.70710678118654752440f));
}

__global__ void bn_gelu_tr_kernel(float* __restrict__ x, const int* __restrict__ subj, int emit)
{
    __shared__ __half sh[128][33];
    __shared__ __half sl[128][33];
    const int tid = threadIdx.x;
    const int b   = blockIdx.y;
    const int c0  = blockIdx.x * 32;
    const int s   = subj[b];

    for (int ts = 0; ts < TLEN; ts += 128) {
        for (int idx = tid; idx < 1024; idx += 256) {
            const int ci = idx >> 5, t4 = idx & 31;
            const int c = c0 + ci;
            const float sc = g_scale[s * COUT + c];
            const float sv = g_shift[s * COUT + c];
            float* xp = &x[((size_t)b * COUT + c) * TLEN + ts + t4 * 4];
            float4 v = *(const float4*)xp;
            v.x = gelu_exact(v.x * sc + sv);
            v.y = gelu_exact(v.y * sc + sv);
            v.z = gelu_exact(v.z * sc + sv);
            v.w = gelu_exact(v.w * sc + sv);
            *(float4*)xp = v;
            if (emit) {
                const float f[4] = {v.x, v.y, v.z, v.w};
                #pragma unroll
                for (int j = 0; j < 4; j++) {
                    const __half h = __float2half(f[j]);
                    sh[t4 * 4 + j][ci] = h;
                    sl[t4 * 4 + j][ci] = __float2half(f[j] - __half2float(h));
                }
            }
        }
        __syncthreads();
        if (emit) {
            for (int idx = tid; idx < 1024; idx += 256) {
                const int arr = idx >> 9;
                const int rem = idx & 511;
                const int r = rem >> 2, q = rem & 3;
                const __half* src = arr ? &sl[r][q * 8] : &sh[r][q * 8];
                uint16_t tmp[8];
                #pragma unroll
                for (int j = 0; j < 8; j++) tmp[j] = ((const uint16_t*)src)[j];
                __half* dst = (arr ? g_lo : g_hi) + ((size_t)b * TLEN + ts + r) * CPAD + c0 + q * 8;
                *(uint4*)dst = *(const uint4*)tmp;
            }
        }
        __syncthreads();
    }
}

// ================= launch =================
extern "C" void kernel_launch(void* const* d_in, const int* in_sizes, int n_in,
                              void* d_out, int out_size)
{
    const float* X    = (const float*)d_in[0];
    const int*   subj = (const int*)  d_in[1];
    const float* w0   = (const float*)d_in[2];
    const float* b0   = (const float*)d_in[3];
    const float* w1   = (const float*)d_in[4];
    const float* b1   = (const float*)d_in[5];
    const float* w2   = (const float*)d_in[6];
    const float* b2   = (const float*)d_in[7];
    const float* g0   = (const float*)d_in[8];
    const float* be0  = (const float*)d_in[9];
    const float* g1   = (const float*)d_in[10];
    const float* be1  = (const float*)d_in[11];
    const float* g2   = (const float*)d_in[12];
    const float* be2  = (const float*)d_in[13];
    float* out = (float*)d_out;

    float* bufA; cudaGetSymbolAddress((void**)&bufA, g_bufA);
    float* bufB; cudaGetSymbolAddress((void**)&bufB, g_bufB);
    __half* xhi; cudaGetSymbolAddress((void**)&xhi, g_hi);
    __half* xlo; cudaGetSymbolAddress((void**)&xlo, g_lo);
    __half* wf;  cudaGetSymbolAddress((void**)&wf,  g_wfmt);
    const size_t wstep = (size_t)6 * 320 * 320;

    cudaFuncSetAttribute(conv_mma_kernel,
                         cudaFuncAttributeMaxDynamicSharedMemorySize, CONV_SMEM);

    const dim3 cgrid(5, 4, BATCH);     // 64-co tiles x 128-t tiles x batch
    const dim3 egrid(10, BATCH);
    const int wfmt_n = 6 * 320 * 320;
    const int rgrid = (NSUBJ * COUT + 255) / 256;

    // ---- prologue (ordered so conv layer-0 is launch index 3 for ncu) ----
    wfmt_kernel<<<(wfmt_n + 255) / 256, 256>>>(w0, 271, 0);      // 0
    convert_x_tr_kernel<<<egrid, 256>>>(X, 271);                 // 1
    wfmt_kernel<<<(wfmt_n + 255) / 256, 256>>>(w1, COUT, 1);     // 2

    // ---- layer 0 ----
    conv_mma_kernel<<<cgrid, 256, CONV_SMEM>>>(xhi, xlo, wf, b0, nullptr, bufA, 17);  // 3
    stats_reduce_g<<<rgrid, 256>>>(subj, g0, be0);
    bn_gelu_tr_kernel<<<egrid, 256>>>(bufA, subj, 1);
    wfmt_kernel<<<(wfmt_n + 255) / 256, 256>>>(w2, COUT, 2);

    // ---- layer 1 ----
    conv_mma_kernel<<<cgrid, 256, CONV_SMEM>>>(xhi, xlo, wf + wstep, b1, bufA, bufB, 20);
    stats_reduce_g<<<rgrid, 256>>>(subj, g1, be1);
    bn_gelu_tr_kernel<<<egrid, 256>>>(bufB, subj, 1);

    // ---- layer 2 ----
    conv_mma_kernel<<<cgrid, 256, CONV_SMEM>>>(xhi, xlo, wf + 2 * wstep, b2, bufB, out, 20);
    stats_reduce_g<<<rgrid, 256>>>(subj, g2, be2);
    bn_gelu_tr_kernel<<<egrid, 256>>>(out, subj, 0);
}

// round 14
// speedup vs baseline: 1.2358x; 1.2358x over previous
#include <cuda_runtime.h>
#include <cuda_fp16.h>
#include <cstdint>
#include <math.h>

#define BATCH 256
#define TLEN  512
#define COUT  320
#define CPAD  320
#define NSUBJ 4
#define EPSBN 1e-5f

// ================= scratch (no allocations allowed) =================
__device__ float g_bufA[(size_t)BATCH * COUT * TLEN];
__device__ float g_bufB[(size_t)BATCH * COUT * TLEN];
__device__ __half g_hi[(size_t)BATCH * TLEN * CPAD];   // [b][t][c] fp16 hi split
__device__ __half g_lo[(size_t)BATCH * TLEN * CPAD];   // [b][t][c] fp16 lo split
__device__ __half g_wfmt[3 * 6 * 320 * 320];           // [layer][(ko*2+sp)][co][ci]
__device__ float g_part1[8 * BATCH * COUT];            // [tt][b][co]
__device__ float g_part2[8 * BATCH * COUT];
__device__ float g_scale[NSUBJ * COUT];
__device__ float g_shift[NSUBJ * COUT];

// ================= mma / ldmatrix / cp.async helpers =================
__device__ __forceinline__ uint32_t smem_addr(const void* p) {
    return (uint32_t)__cvta_generic_to_shared(p);
}
__device__ __forceinline__ void ldsm_x4(uint32_t* r, uint32_t addr) {
    asm volatile("ldmatrix.sync.aligned.m8n8.x4.shared.b16 {%0,%1,%2,%3}, [%4];"
                 : "=r"(r[0]), "=r"(r[1]), "=r"(r[2]), "=r"(r[3]) : "r"(addr));
}
__device__ __forceinline__ void ldsm_x2(uint32_t* r, uint32_t addr) {
    asm volatile("ldmatrix.sync.aligned.m8n8.x2.shared.b16 {%0,%1}, [%2];"
                 : "=r"(r[0]), "=r"(r[1]) : "r"(addr));
}
__device__ __forceinline__ void mma_f32(float* c, const uint32_t* a, const uint32_t* b) {
    asm volatile("mma.sync.aligned.m16n8k16.row.col.f32.f16.f16.f32 "
                 "{%0,%1,%2,%3}, {%4,%5,%6,%7}, {%8,%9}, {%0,%1,%2,%3};"
                 : "+f"(c[0]), "+f"(c[1]), "+f"(c[2]), "+f"(c[3])
                 : "r"(a[0]), "r"(a[1]), "r"(a[2]), "r"(a[3]), "r"(b[0]), "r"(b[1]));
}
__device__ __forceinline__ void mma_f16(uint32_t* c, const uint32_t* a, const uint32_t* b) {
    asm volatile("mma.sync.aligned.m16n8k16.row.col.f16.f16.f16.f16 "
                 "{%0,%1}, {%2,%3,%4,%5}, {%6,%7}, {%0,%1};"
                 : "+r"(c[0]), "+r"(c[1])
                 : "r"(a[0]), "r"(a[1]), "r"(a[2]), "r"(a[3]), "r"(b[0]), "r"(b[1]));
}
__device__ __forceinline__ void cp16(uint32_t dst, const void* src) {
    asm volatile("cp.async.cg.shared.global [%0], [%1], 16;" :: "r"(dst), "l"(src));
}
__device__ __forceinline__ void cp16z(uint32_t dst, const void* src, int sz) {
    asm volatile("cp.async.cg.shared.global [%0], [%1], 16, %2;" :: "r"(dst), "l"(src), "r"(sz));
}
#define CP_COMMIT() asm volatile("cp.async.commit_group;")
#define CP_WAIT(n)  asm volatile("cp.async.wait_group %0;" :: "n"(n))

// 64B-row swizzle: 16B-half selector, conflict-free ldsm 8-row phases
#define SWH2(r, h) ((h) ^ ((r) & 3) ^ (((r) >> 2) & 1))

// ================= conv via warp MMA, K=32 stages =================
// CTA tile: 128 t x 64 co; 8 warps (4 t x 2 co); warp tile 32t x 32co.
// A = X^T smem [row=t][32 ci] (tap = +ko rows), B = W smem [co][32 ci].
// Products: f32acc hi*Whi; f16acc (hi*Wlo + lo*Whi).
#define XROWS   132
#define XSLAB   (XROWS * 64)             // 8448 B per split slab
#define XSTG    (2 * XSLAB)              // 16896 B per stage
#define WTILE   (64 * 64)                // 4096 B per (ko,sp) tile
#define WSTG    (6 * WTILE)              // 24576 B per stage
#define WBASE   (2 * XSTG)               // 33792
#define CONV_SMEM (WBASE + 2 * WSTG)     // 82944 B

__global__ __launch_bounds__(256, 2)
void conv_mma_kernel(const __half* __restrict__ xhi,
                     const __half* __restrict__ xlo,
                     const __half* __restrict__ wf,
                     const float* __restrict__ bias,
                     const float* __restrict__ resid,
                     float* __restrict__ out,
                     int nch)
{
    extern __shared__ char smem[];
    const uint32_t sb = smem_addr(smem);

    const int tid  = threadIdx.x;
    const int wid  = tid >> 5;
    const int lane = tid & 31;
    const int co_blk = blockIdx.x * 64;
    const int t0     = blockIdx.y * 128;
    const int b      = blockIdx.z;

    const int warp_t0  = (wid >> 1) * 32;      // 0,32,64,96
    const int warp_co0 = (wid & 1) * 32;       // 0,32

    float    acc[2][4][4];
    uint32_t cacc[2][4][2];
    #pragma unroll
    for (int m = 0; m < 2; m++)
        #pragma unroll
        for (int n = 0; n < 4; n++) {
            #pragma unroll
            for (int k = 0; k < 4; k++) acc[m][n][k] = 0.f;
            cacc[m][n][0] = 0u; cacc[m][n][1] = 0u;
        }

    const int a_row = lane & 15, a_h = lane >> 4;          // row, 16B-half within k16
    const int b_row = lane & 7,  b_h = (lane >> 3) & 1;

    // trivial-index load mapping: lrow = tid>>2, lh = tid&3
    const int lrow = tid >> 2, lh = tid & 3;

    auto load_chunk = [&](int ch, int st) {
        const int c0 = ch * 32;
        // X: 2 splits x 130 rows x 4 halves
        #pragma unroll
        for (int sp = 0; sp < 2; sp++) {
            const __half* xb = sp ? xlo : xhi;
            #pragma unroll
            for (int pass = 0; pass < 3; pass++) {
                const int row = pass * 64 + lrow;
                if (row < 130) {
                    const int t  = t0 - 1 + row;
                    const int tc = t < 0 ? 0 : (t > TLEN - 1 ? TLEN - 1 : t);
                    const __half* src = xb + ((size_t)b * TLEN + tc) * CPAD + c0 + lh * 8;
                    const uint32_t dst = sb + st * XSTG + sp * XSLAB + row * 64 + SWH2(row, lh) * 16;
                    cp16z(dst, src, (t >= 0 && t < TLEN) ? 16 : 0);
                }
            }
        }
        // W: 6 tiles x 64 co x 4 halves
        #pragma unroll
        for (int tile = 0; tile < 6; tile++) {
            const __half* src = wf + ((size_t)tile * 320 + co_blk + lrow) * 320 + c0 + lh * 8;
            const uint32_t dst = sb + WBASE + st * WSTG + tile * WTILE + lrow * 64 + SWH2(lrow, lh) * 16;
            cp16(dst, src);
        }
        CP_COMMIT();
    };

    load_chunk(0, 0);

    for (int ch = 0; ch < nch; ch++) {
        const int st = ch & 1;
        if (ch + 1 < nch) { load_chunk(ch + 1, st ^ 1); CP_WAIT(1); }
        else              { CP_WAIT(0); }
        __syncthreads();

        const uint32_t xhi_b = sb + st * XSTG;
        const uint32_t xlo_b = xhi_b + XSLAB;
        const uint32_t wb    = sb + WBASE + st * WSTG;

        #pragma unroll
        for (int kk = 0; kk < 2; kk++) {
            #pragma unroll
            for (int ko = 0; ko < 3; ko++) {
                uint32_t bh[4][2], bl[4][2];
                #pragma unroll
                for (int n = 0; n < 4; n++) {
                    const int wr = warp_co0 + n * 8 + b_row;
                    const int hh = kk * 2 + b_h;
                    const uint32_t woff = (uint32_t)(wr * 64 + SWH2(wr, hh) * 16);
                    ldsm_x2(bh[n], wb + (ko * 2 + 0) * WTILE + woff);
                    ldsm_x2(bl[n], wb + (ko * 2 + 1) * WTILE + woff);
                }
                uint32_t a[2][4];
                #pragma unroll
                for (int m = 0; m < 2; m++) {
                    const int xr = warp_t0 + m * 16 + ko + a_row;
                    const int hh = kk * 2 + a_h;
                    ldsm_x4(a[m], xhi_b + (uint32_t)(xr * 64 + SWH2(xr, hh) * 16));
                }
                #pragma unroll
                for (int m = 0; m < 2; m++)
                    #pragma unroll
                    for (int n = 0; n < 4; n++) mma_f32(acc[m][n], a[m], bh[n]);
                #pragma unroll
                for (int m = 0; m < 2; m++)
                    #pragma unroll
                    for (int n = 0; n < 4; n++) mma_f16(cacc[m][n], a[m], bl[n]);
                #pragma unroll
                for (int m = 0; m < 2; m++) {
                    const int xr = warp_t0 + m * 16 + ko + a_row;
                    const int hh = kk * 2 + a_h;
                    ldsm_x4(a[m], xlo_b + (uint32_t)(xr * 64 + SWH2(xr, hh) * 16));
                }
                #pragma unroll
                for (int m = 0; m < 2; m++)
                    #pragma unroll
                    for (int n = 0; n < 4; n++) mma_f16(cacc[m][n], a[m], bh[n]);
            }
        }
        __syncthreads();
    }

    // ---- epilogue: two 64-t halves via smem transpose; fused BN partial stats ----
    float* sO = (float*)smem;                   // [64 co][68 t] = 17408 B
    #pragma unroll
    for (int th = 0; th < 2; th++) {
        if ((warp_t0 >> 6) == th) {
            const int tb2 = warp_t0 & 63;       // 0 or 32
            const int t_l = lane >> 2;
            #pragma unroll
            for (int n = 0; n < 4; n++) {
                const int co_l = warp_co0 + n * 8 + ((lane & 3) << 1);
                #pragma unroll
                for (int m = 0; m < 2; m++) {
                    const int t = tb2 + m * 16 + t_l;
                    const __half2 h0 = *reinterpret_cast<const __half2*>(&cacc[m][n][0]);
                    const __half2 h1 = *reinterpret_cast<const __half2*>(&cacc[m][n][1]);
                    sO[co_l * 68 + t]           = acc[m][n][0] + __low2float(h0);
                    sO[(co_l + 1) * 68 + t]     = acc[m][n][1] + __high2float(h0);
                    sO[co_l * 68 + t + 8]       = acc[m][n][2] + __low2float(h1);
                    sO[(co_l + 1) * 68 + t + 8] = acc[m][n][3] + __high2float(h1);
                }
            }
        }
        __syncthreads();

        const int tt = blockIdx.y * 2 + th;
        for (int idx = tid; idx < 64 * 16; idx += 256) {
            const int co = idx >> 4, t4 = idx & 15;
            float4 v = *(const float4*)&sO[co * 68 + t4 * 4];
            const float bv = bias[co_blk + co];
            v.x += bv; v.y += bv; v.z += bv; v.w += bv;
            const size_t adr = ((size_t)b * COUT + co_blk + co) * TLEN + t0 + th * 64 + t4 * 4;
            if (resid) {
                const float4 r = *(const float4*)&resid[adr];
                v.x += r.x; v.y += r.y; v.z += r.z; v.w += r.w;
            }
            *(float4*)&out[adr] = v;
            float s = v.x + v.y + v.z + v.w;
            float q = v.x * v.x + v.y * v.y + v.z * v.z + v.w * v.w;
            #pragma unroll
            for (int o = 8; o > 0; o >>= 1) {
                s += __shfl_down_sync(0xffffffffu, s, o, 16);
                q += __shfl_down_sync(0xffffffffu, q, o, 16);
            }
            if ((lane & 15) == 0) {
                const size_t pa = ((size_t)tt * BATCH + b) * COUT + co_blk + co;
                g_part1[pa] = s;
                g_part2[pa] = q;
            }
        }
        __syncthreads();
    }
}

// ================= weight reformat: [(ko*2+sp)][co320][ci320] fp16 =================
__global__ void wfmt_kernel(const float* __restrict__ W, int Cin, int layer)
{
    const int idx = blockIdx.x * blockDim.x + threadIdx.x;
    if (idx >= 6 * 320 * 320) return;
    const int ci = idx % 320;
    const int co = (idx / 320) % 320;
    const int ts = idx / (320 * 320);
    const int ko = ts >> 1, sp = ts & 1;
    float v = 0.f;
    if (ci < Cin) v = W[((size_t)co * Cin + ci) * 3 + ko];
    const __half h = __float2half(v);
    g_wfmt[(size_t)layer * 6 * 320 * 320 + idx] =
        (sp == 0) ? h : __float2half(v - __half2float(h));
}

// ================= input convert: X fp32 [b][Cin][512] -> hi/lo [b][t][320] =================
__global__ void convert_x_tr_kernel(const float* __restrict__ x, int Cin)
{
    __shared__ __half sh[128][33];
    __shared__ __half sl[128][33];
    const int tid = threadIdx.x;
    const int b   = blockIdx.y;
    const int c0  = blockIdx.x * 32;

    for (int ts = 0; ts < TLEN; ts += 128) {
        for (int idx = tid; idx < 1024; idx += 256) {
            const int ci = idx >> 5, t4 = idx & 31;
            const int c = c0 + ci;
            float4 v = make_float4(0.f, 0.f, 0.f, 0.f);
            if (c < Cin) v = *(const float4*)&x[((size_t)b * Cin + c) * TLEN + ts + t4 * 4];
            const float f[4] = {v.x, v.y, v.z, v.w};
            #pragma unroll
            for (int j = 0; j < 4; j++) {
                const __half h = __float2half(f[j]);
                sh[t4 * 4 + j][ci] = h;
                sl[t4 * 4 + j][ci] = __float2half(f[j] - __half2float(h));
            }
        }
        __syncthreads();
        for (int idx = tid; idx < 1024; idx += 256) {
            const int arr = idx >> 9;
            const int rem = idx & 511;
            const int r = rem >> 2, q = rem & 3;
            const __half* src = arr ? &sl[r][q * 8] : &sh[r][q * 8];
            uint16_t tmp[8];
            #pragma unroll
            for (int j = 0; j < 8; j++) tmp[j] = ((const uint16_t*)src)[j];
            __half* dst = (arr ? g_lo : g_hi) + ((size_t)b * TLEN + ts + r) * CPAD + c0 + q * 8;
            *(uint4*)dst = *(const uint4*)tmp;
        }
        __syncthreads();
    }
}

// ====== BN stats reduce: one block per (s,c), deterministic tree ======
__global__ __launch_bounds__(128)
void stats_reduce_g(const int* __restrict__ subj,
                    const float* __restrict__ gamma, const float* __restrict__ beta)
{
    __shared__ float ss[128], sq[128];
    __shared__ int   sn[128];
    const int bid = blockIdx.x;            // s*COUT + c
    const int c   = bid % COUT;
    const int s   = bid / COUT;
    const int tid = threadIdx.x;

    float sum = 0.f, q = 0.f;
    int nb = 0;
    #pragma unroll
    for (int half = 0; half < 2; half++) {
        const int b = half * 128 + tid;
        if (subj[b] == s) {
            nb++;
            #pragma unroll
            for (int tt = 0; tt < 8; tt++) {
                const size_t pa = ((size_t)tt * BATCH + b) * COUT + c;
                sum += g_part1[pa];
                q   += g_part2[pa];
            }
        }
    }
    ss[tid] = sum; sq[tid] = q; sn[tid] = nb;
    __syncthreads();
    #pragma unroll
    for (int o = 64; o > 0; o >>= 1) {
        if (tid < o) {
            ss[tid] += ss[tid + o];
            sq[tid] += sq[tid + o];
            sn[tid] += sn[tid + o];
        }
        __syncthreads();
    }
    if (tid == 0) {
        const float cnt  = fmaxf((float)sn[0] * (float)TLEN, 1.0f);
        const float mean = ss[0] / cnt;
        const float var  = sq[0] / cnt - mean * mean;
        const float sc   = gamma[bid] * rsqrtf(var + EPSBN);
        g_scale[bid] = sc;
        g_shift[bid] = beta[bid] - mean * sc;
    }
}

// ====== BN apply + exact GELU (in place) + transposed hi/lo emit ======
__device__ __forceinline__ float gelu_exact(float y) {
    return 0.5f * y * (1.0f + erff(y * 0.70710678118654752440f));
}

__global__ void bn_gelu_tr_kernel(float* __restrict__ x, const int* __restrict__ subj, int emit)
{
    __shared__ __half sh[128][33];
    __shared__ __half sl[128][33];
    const int tid = threadIdx.x;
    const int b   = blockIdx.y;
    const int c0  = blockIdx.x * 32;
    const int s   = subj[b];

    for (int ts = 0; ts < TLEN; ts += 128) {
        for (int idx = tid; idx < 1024; idx += 256) {
            const int ci = idx >> 5, t4 = idx & 31;
            const int c = c0 + ci;
            const float sc = g_scale[s * COUT + c];
            const float sv = g_shift[s * COUT + c];
            float* xp = &x[((size_t)b * COUT + c) * TLEN + ts + t4 * 4];
            float4 v = *(const float4*)xp;
            v.x = gelu_exact(v.x * sc + sv);
            v.y = gelu_exact(v.y * sc + sv);
            v.z = gelu_exact(v.z * sc + sv);
            v.w = gelu_exact(v.w * sc + sv);
            *(float4*)xp = v;
            if (emit) {
                const float f[4] = {v.x, v.y, v.z, v.w};
                #pragma unroll
                for (int j = 0; j < 4; j++) {
                    const __half h = __float2half(f[j]);
                    sh[t4 * 4 + j][ci] = h;
                    sl[t4 * 4 + j][ci] = __float2half(f[j] - __half2float(h));
                }
            }
        }
        __syncthreads();
        if (emit) {
            for (int idx = tid; idx < 1024; idx += 256) {
                const int arr = idx >> 9;
                const int rem = idx & 511;
                const int r = rem >> 2, q = rem & 3;
                const __half* src = arr ? &sl[r][q * 8] : &sh[r][q * 8];
                uint16_t tmp[8];
                #pragma unroll
                for (int j = 0; j < 8; j++) tmp[j] = ((const uint16_t*)src)[j];
                __half* dst = (arr ? g_lo : g_hi) + ((size_t)b * TLEN + ts + r) * CPAD + c0 + q * 8;
                *(uint4*)dst = *(const uint4*)tmp;
            }
        }
        __syncthreads();
    }
}

// ================= launch =================
extern "C" void kernel_launch(void* const* d_in, const int* in_sizes, int n_in,
                              void* d_out, int out_size)
{
    const float* X    = (const float*)d_in[0];
    const int*   subj = (const int*)  d_in[1];
    const float* w0   = (const float*)d_in[2];
    const float* b0   = (const float*)d_in[3];
    const float* w1   = (const float*)d_in[4];
    const float* b1   = (const float*)d_in[5];
    const float* w2   = (const float*)d_in[6];
    const float* b2   = (const float*)d_in[7];
    const float* g0   = (const float*)d_in[8];
    const float* be0  = (const float*)d_in[9];
    const float* g1   = (const float*)d_in[10];
    const float* be1  = (const float*)d_in[11];
    const float* g2   = (const float*)d_in[12];
    const float* be2  = (const float*)d_in[13];
    float* out = (float*)d_out;

    float* bufA; cudaGetSymbolAddress((void**)&bufA, g_bufA);
    float* bufB; cudaGetSymbolAddress((void**)&bufB, g_bufB);
    __half* xhi; cudaGetSymbolAddress((void**)&xhi, g_hi);
    __half* xlo; cudaGetSymbolAddress((void**)&xlo, g_lo);
    __half* wf;  cudaGetSymbolAddress((void**)&wf,  g_wfmt);
    const size_t wstep = (size_t)6 * 320 * 320;

    cudaFuncSetAttribute(conv_mma_kernel,
                         cudaFuncAttributeMaxDynamicSharedMemorySize, CONV_SMEM);

    const dim3 cgrid(5, 4, BATCH);     // 64-co tiles x 128-t tiles x batch
    const dim3 egrid(10, BATCH);
    const int wfmt_n = 6 * 320 * 320;

    // ---- prologue (conv layer-0 kept at launch index 3 for ncu) ----
    wfmt_kernel<<<(wfmt_n + 255) / 256, 256>>>(w0, 271, 0);      // 0
    convert_x_tr_kernel<<<egrid, 256>>>(X, 271);                 // 1
    wfmt_kernel<<<(wfmt_n + 255) / 256, 256>>>(w1, COUT, 1);     // 2

    // ---- layer 0 (272 ci padded -> 9 chunks of 32) ----
    conv_mma_kernel<<<cgrid, 256, CONV_SMEM>>>(xhi, xlo, wf, b0, nullptr, bufA, 9);   // 3
    stats_reduce_g<<<NSUBJ * COUT, 128>>>(subj, g0, be0);
    bn_gelu_tr_kernel<<<egrid, 256>>>(bufA, subj, 1);
    wfmt_kernel<<<(wfmt_n + 255) / 256, 256>>>(w2, COUT, 2);

    // ---- layer 1 ----
    conv_mma_kernel<<<cgrid, 256, CONV_SMEM>>>(xhi, xlo, wf + wstep, b1, bufA, bufB, 10);
    stats_reduce_g<<<NSUBJ * COUT, 128>>>(subj, g1, be1);
    bn_gelu_tr_kernel<<<egrid, 256>>>(bufB, subj, 1);

    // ---- layer 2 ----
    conv_mma_kernel<<<cgrid, 256, CONV_SMEM>>>(xhi, xlo, wf + 2 * wstep, b2, bufB, out, 10);
    stats_reduce_g<<<NSUBJ * COUT, 128>>>(subj, g2, be2);
    bn_gelu_tr_kernel<<<egrid, 256>>>(out, subj, 0);
}

// round 15
// speedup vs baseline: 1.5873x; 1.2844x over previous
#include <cuda_runtime.h>
#include <cuda_fp16.h>
#include <cstdint>
#include <math.h>

#define BATCH 256
#define TLEN  512
#define COUT  320
#define CPAD  320
#define NSUBJ 4
#define EPSBN 1e-5f

// ================= scratch (no allocations allowed) =================
__device__ float g_bufA[(size_t)BATCH * COUT * TLEN];
__device__ float g_bufB[(size_t)BATCH * COUT * TLEN];
__device__ __half g_hi[(size_t)BATCH * TLEN * CPAD];   // [b][t][c] fp16 hi split
__device__ __half g_lo[(size_t)BATCH * TLEN * CPAD];   // [b][t][c] fp16 lo split
__device__ __half g_wfmt[3 * 3 * 320 * 320];           // [layer][ko][co][ci] fp16 weights
__device__ float g_part1[8 * BATCH * COUT];            // [tt][b][co]
__device__ float g_part2[8 * BATCH * COUT];
__device__ float g_scale[NSUBJ * COUT];
__device__ float g_shift[NSUBJ * COUT];

// ================= mma / ldmatrix / cp.async helpers =================
__device__ __forceinline__ uint32_t smem_addr(const void* p) {
    return (uint32_t)__cvta_generic_to_shared(p);
}
__device__ __forceinline__ void ldsm_x4(uint32_t* r, uint32_t addr) {
    asm volatile("ldmatrix.sync.aligned.m8n8.x4.shared.b16 {%0,%1,%2,%3}, [%4];"
                 : "=r"(r[0]), "=r"(r[1]), "=r"(r[2]), "=r"(r[3]) : "r"(addr));
}
__device__ __forceinline__ void ldsm_x2(uint32_t* r, uint32_t addr) {
    asm volatile("ldmatrix.sync.aligned.m8n8.x2.shared.b16 {%0,%1}, [%2];"
                 : "=r"(r[0]), "=r"(r[1]) : "r"(addr));
}
__device__ __forceinline__ void mma_f32(float* c, const uint32_t* a, const uint32_t* b) {
    asm volatile("mma.sync.aligned.m16n8k16.row.col.f32.f16.f16.f32 "
                 "{%0,%1,%2,%3}, {%4,%5,%6,%7}, {%8,%9}, {%0,%1,%2,%3};"
                 : "+f"(c[0]), "+f"(c[1]), "+f"(c[2]), "+f"(c[3])
                 : "r"(a[0]), "r"(a[1]), "r"(a[2]), "r"(a[3]), "r"(b[0]), "r"(b[1]));
}
__device__ __forceinline__ void mma_f16(uint32_t* c, const uint32_t* a, const uint32_t* b) {
    asm volatile("mma.sync.aligned.m16n8k16.row.col.f16.f16.f16.f16 "
                 "{%0,%1}, {%2,%3,%4,%5}, {%6,%7}, {%0,%1};"
                 : "+r"(c[0]), "+r"(c[1])
                 : "r"(a[0]), "r"(a[1]), "r"(a[2]), "r"(a[3]), "r"(b[0]), "r"(b[1]));
}
__device__ __forceinline__ void cp16(uint32_t dst, const void* src) {
    asm volatile("cp.async.cg.shared.global [%0], [%1], 16;" :: "r"(dst), "l"(src));
}
__device__ __forceinline__ void cp16z(uint32_t dst, const void* src, int sz) {
    asm volatile("cp.async.cg.shared.global [%0], [%1], 16, %2;" :: "r"(dst), "l"(src), "r"(sz));
}
#define CP_COMMIT() asm volatile("cp.async.commit_group;")
#define CP_WAIT(n)  asm volatile("cp.async.wait_group %0;" :: "n"(n))

// 64B-row swizzle: 16B-half selector, conflict-free ldsm 8-row phases
#define SWH2(r, h) ((h) ^ ((r) & 3) ^ (((r) >> 2) & 1))

// ================= conv via warp MMA, K=32 stages =================
// CTA tile: 128 t x 64 co; 8 warps (4 t x 2 co); warp tile 32t x 32co.
// A = X^T smem [row=t][32 ci] (tap = +ko rows), B = Whi smem [co][32 ci].
// Products: f32acc hi*Whi (main) + f16acc lo*Whi (x-rounding correction).
// Weights committed to fp16 (W ~= Whi): output rel err ~2.5e-4 << 1e-3.
#define XROWS   132
#define XSLAB   (XROWS * 64)             // 8448 B per split slab
#define XSTG    (2 * XSLAB)              // 16896 B per stage
#define WTILE   (64 * 64)                // 4096 B per ko tile
#define WSTG    (3 * WTILE)              // 12288 B per stage
#define WBASE   (2 * XSTG)               // 33792
#define CONV_SMEM (WBASE + 2 * WSTG)     // 58368 B

__global__ __launch_bounds__(256, 2)
void conv_mma_kernel(const __half* __restrict__ xhi,
                     const __half* __restrict__ xlo,
                     const __half* __restrict__ wf,
                     const float* __restrict__ bias,
                     const float* __restrict__ resid,
                     float* __restrict__ out,
                     int nch)
{
    extern __shared__ char smem[];
    const uint32_t sb = smem_addr(smem);

    const int tid  = threadIdx.x;
    const int wid  = tid >> 5;
    const int lane = tid & 31;
    const int co_blk = blockIdx.x * 64;
    const int t0     = blockIdx.y * 128;
    const int b      = blockIdx.z;

    const int warp_t0  = (wid >> 1) * 32;      // 0,32,64,96
    const int warp_co0 = (wid & 1) * 32;       // 0,32

    float    acc[2][4][4];
    uint32_t cacc[2][4][2];
    #pragma unroll
    for (int m = 0; m < 2; m++)
        #pragma unroll
        for (int n = 0; n < 4; n++) {
            #pragma unroll
            for (int k = 0; k < 4; k++) acc[m][n][k] = 0.f;
            cacc[m][n][0] = 0u; cacc[m][n][1] = 0u;
        }

    const int a_row = lane & 15, a_h = lane >> 4;          // row, 16B-half within k16
    const int b_row = lane & 7,  b_h = (lane >> 3) & 1;

    // trivial-index load mapping
    const int lrow = tid >> 2, lh = tid & 3;

    auto load_chunk = [&](int ch, int st) {
        const int c0 = ch * 32;
        // X: 2 splits x 130 rows x 4 halves
        #pragma unroll
        for (int sp = 0; sp < 2; sp++) {
            const __half* xb = sp ? xlo : xhi;
            #pragma unroll
            for (int pass = 0; pass < 3; pass++) {
                const int row = pass * 64 + lrow;
                if (row < 130) {
                    const int t  = t0 - 1 + row;
                    const int tc = t < 0 ? 0 : (t > TLEN - 1 ? TLEN - 1 : t);
                    const __half* src = xb + ((size_t)b * TLEN + tc) * CPAD + c0 + lh * 8;
                    const uint32_t dst = sb + st * XSTG + sp * XSLAB + row * 64 + SWH2(row, lh) * 16;
                    cp16z(dst, src, (t >= 0 && t < TLEN) ? 16 : 0);
                }
            }
        }
        // W: 3 ko tiles x 64 co x 4 halves
        #pragma unroll
        for (int tile = 0; tile < 3; tile++) {
            const __half* src = wf + ((size_t)tile * 320 + co_blk + lrow) * 320 + c0 + lh * 8;
            const uint32_t dst = sb + WBASE + st * WSTG + tile * WTILE + lrow * 64 + SWH2(lrow, lh) * 16;
            cp16(dst, src);
        }
        CP_COMMIT();
    };

    load_chunk(0, 0);

    for (int ch = 0; ch < nch; ch++) {
        const int st = ch & 1;
        if (ch + 1 < nch) { load_chunk(ch + 1, st ^ 1); CP_WAIT(1); }
        else              { CP_WAIT(0); }
        __syncthreads();

        const uint32_t xhi_b = sb + st * XSTG;
        const uint32_t xlo_b = xhi_b + XSLAB;
        const uint32_t wb    = sb + WBASE + st * WSTG;

        #pragma unroll
        for (int kk = 0; kk < 2; kk++) {
            #pragma unroll
            for (int ko = 0; ko < 3; ko++) {
                uint32_t bh[4][2];
                #pragma unroll
                for (int n = 0; n < 4; n++) {
                    const int wr = warp_co0 + n * 8 + b_row;
                    const int hh = kk * 2 + b_h;
                    ldsm_x2(bh[n], wb + ko * WTILE + (uint32_t)(wr * 64 + SWH2(wr, hh) * 16));
                }
                uint32_t a[2][4];
                #pragma unroll
                for (int m = 0; m < 2; m++) {
                    const int xr = warp_t0 + m * 16 + ko + a_row;
                    const int hh = kk * 2 + a_h;
                    ldsm_x4(a[m], xhi_b + (uint32_t)(xr * 64 + SWH2(xr, hh) * 16));
                }
                #pragma unroll
                for (int m = 0; m < 2; m++)
                    #pragma unroll
                    for (int n = 0; n < 4; n++) mma_f32(acc[m][n], a[m], bh[n]);
                #pragma unroll
                for (int m = 0; m < 2; m++) {
                    const int xr = warp_t0 + m * 16 + ko + a_row;
                    const int hh = kk * 2 + a_h;
                    ldsm_x4(a[m], xlo_b + (uint32_t)(xr * 64 + SWH2(xr, hh) * 16));
                }
                #pragma unroll
                for (int m = 0; m < 2; m++)
                    #pragma unroll
                    for (int n = 0; n < 4; n++) mma_f16(cacc[m][n], a[m], bh[n]);
            }
        }
        __syncthreads();
    }

    // ---- epilogue: two 64-t halves via smem transpose; fused BN partial stats ----
    float* sO = (float*)smem;                   // [64 co][68 t] = 17408 B
    #pragma unroll
    for (int th = 0; th < 2; th++) {
        if ((warp_t0 >> 6) == th) {
            const int tb2 = warp_t0 & 63;       // 0 or 32
            const int t_l = lane >> 2;
            #pragma unroll
            for (int n = 0; n < 4; n++) {
                const int co_l = warp_co0 + n * 8 + ((lane & 3) << 1);
                #pragma unroll
                for (int m = 0; m < 2; m++) {
                    const int t = tb2 + m * 16 + t_l;
                    const __half2 h0 = *reinterpret_cast<const __half2*>(&cacc[m][n][0]);
                    const __half2 h1 = *reinterpret_cast<const __half2*>(&cacc[m][n][1]);
                    sO[co_l * 68 + t]           = acc[m][n][0] + __low2float(h0);
                    sO[(co_l + 1) * 68 + t]     = acc[m][n][1] + __high2float(h0);
                    sO[co_l * 68 + t + 8]       = acc[m][n][2] + __low2float(h1);
                    sO[(co_l + 1) * 68 + t + 8] = acc[m][n][3] + __high2float(h1);
                }
            }
        }
        __syncthreads();

        const int tt = blockIdx.y * 2 + th;
        for (int idx = tid; idx < 64 * 16; idx += 256) {
            const int co = idx >> 4, t4 = idx & 15;
            float4 v = *(const float4*)&sO[co * 68 + t4 * 4];
            const float bv = bias[co_blk + co];
            v.x += bv; v.y += bv; v.z += bv; v.w += bv;
            const size_t adr = ((size_t)b * COUT + co_blk + co) * TLEN + t0 + th * 64 + t4 * 4;
            if (resid) {
                const float4 r = *(const float4*)&resid[adr];
                v.x += r.x; v.y += r.y; v.z += r.z; v.w += r.w;
            }
            *(float4*)&out[adr] = v;
            float s = v.x + v.y + v.z + v.w;
            float q = v.x * v.x + v.y * v.y + v.z * v.z + v.w * v.w;
            #pragma unroll
            for (int o = 8; o > 0; o >>= 1) {
                s += __shfl_down_sync(0xffffffffu, s, o, 16);
                q += __shfl_down_sync(0xffffffffu, q, o, 16);
            }
            if ((lane & 15) == 0) {
                const size_t pa = ((size_t)tt * BATCH + b) * COUT + co_blk + co;
                g_part1[pa] = s;
                g_part2[pa] = q;
            }
        }
        __syncthreads();
    }
}

// ================= weight reformat: [ko][co320][ci320] fp16 =================
__global__ void wfmt_kernel(const float* __restrict__ W, int Cin, int layer)
{
    const int idx = blockIdx.x * blockDim.x + threadIdx.x;
    if (idx >= 3 * 320 * 320) return;
    const int ci = idx % 320;
    const int co = (idx / 320) % 320;
    const int ko = idx / (320 * 320);
    float v = 0.f;
    if (ci < Cin) v = W[((size_t)co * Cin + ci) * 3 + ko];
    g_wfmt[(size_t)layer * 3 * 320 * 320 + idx] = __float2half(v);
}

// ================= input convert: X fp32 [b][Cin][512] -> hi/lo [b][t][320] =================
__global__ void convert_x_tr_kernel(const float* __restrict__ x, int Cin)
{
    __shared__ __half sh[128][33];
    __shared__ __half sl[128][33];
    const int tid = threadIdx.x;
    const int b   = blockIdx.y;
    const int c0  = blockIdx.x * 32;

    for (int ts = 0; ts < TLEN; ts += 128) {
        for (int idx = tid; idx < 1024; idx += 256) {
            const int ci = idx >> 5, t4 = idx & 31;
            const int c = c0 + ci;
            float4 v = make_float4(0.f, 0.f, 0.f, 0.f);
            if (c < Cin) v = *(const float4*)&x[((size_t)b * Cin + c) * TLEN + ts + t4 * 4];
            const float f[4] = {v.x, v.y, v.z, v.w};
            #pragma unroll
            for (int j = 0; j < 4; j++) {
                const __half h = __float2half(f[j]);
                sh[t4 * 4 + j][ci] = h;
                sl[t4 * 4 + j][ci] = __float2half(f[j] - __half2float(h));
            }
        }
        __syncthreads();
        for (int idx = tid; idx < 1024; idx += 256) {
            const int arr = idx >> 9;
            const int rem = idx & 511;
            const int r = rem >> 2, q = rem & 3;
            const __half* src = arr ? &sl[r][q * 8] : &sh[r][q * 8];
            uint16_t tmp[8];
            #pragma unroll
            for (int j = 0; j < 8; j++) tmp[j] = ((const uint16_t*)src)[j];
            __half* dst = (arr ? g_lo : g_hi) + ((size_t)b * TLEN + ts + r) * CPAD + c0 + q * 8;
            *(uint4*)dst = *(const uint4*)tmp;
        }
        __syncthreads();
    }
}

// ====== BN stats reduce: one block per (s,c), deterministic tree ======
__global__ __launch_bounds__(128)
void stats_reduce_g(const int* __restrict__ subj,
                    const float* __restrict__ gamma, const float* __restrict__ beta)
{
    __shared__ float ss[128], sq[128];
    __shared__ int   sn[128];
    const int bid = blockIdx.x;            // s*COUT + c
    const int c   = bid % COUT;
    const int s   = bid / COUT;
    const int tid = threadIdx.x;

    float sum = 0.f, q = 0.f;
    int nb = 0;
    #pragma unroll
    for (int half = 0; half < 2; half++) {
        const int b = half * 128 + tid;
        if (subj[b] == s) {
            nb++;
            #pragma unroll
            for (int tt = 0; tt < 8; tt++) {
                const size_t pa = ((size_t)tt * BATCH + b) * COUT + c;
                sum += g_part1[pa];
                q   += g_part2[pa];
            }
        }
    }
    ss[tid] = sum; sq[tid] = q; sn[tid] = nb;
    __syncthreads();
    #pragma unroll
    for (int o = 64; o > 0; o >>= 1) {
        if (tid < o) {
            ss[tid] += ss[tid + o];
            sq[tid] += sq[tid + o];
            sn[tid] += sn[tid + o];
        }
        __syncthreads();
    }
    if (tid == 0) {
        const float cnt  = fmaxf((float)sn[0] * (float)TLEN, 1.0f);
        const float mean = ss[0] / cnt;
        const float var  = sq[0] / cnt - mean * mean;
        const float sc   = gamma[bid] * rsqrtf(var + EPSBN);
        g_scale[bid] = sc;
        g_shift[bid] = beta[bid] - mean * sc;
    }
}

// ====== BN apply + exact GELU (in place) + transposed hi/lo emit ======
__device__ __forceinline__ float gelu_exact(float y) {
    return 0.5f * y * (1.0f + erff(y * 0.70710678118654752440f));
}

__global__ void bn_gelu_tr_kernel(float* __restrict__ x, const int* __restrict__ subj, int emit)
{
    __shared__ __half sh[128][33];
    __shared__ __half sl[128][33];
    const int tid = threadIdx.x;
    const int b   = blockIdx.y;
    const int c0  = blockIdx.x * 32;
    const int s   = subj[b];

    for (int ts = 0; ts < TLEN; ts += 128) {
        for (int idx = tid; idx < 1024; idx += 256) {
            const int ci = idx >> 5, t4 = idx & 31;
            const int c = c0 + ci;
            const float sc = g_scale[s * COUT + c];
            const float sv = g_shift[s * COUT + c];
            float* xp = &x[((size_t)b * COUT + c) * TLEN + ts + t4 * 4];
            float4 v = *(const float4*)xp;
            v.x = gelu_exact(v.x * sc + sv);
            v.y = gelu_exact(v.y * sc + sv);
            v.z = gelu_exact(v.z * sc + sv);
            v.w = gelu_exact(v.w * sc + sv);
            *(float4*)xp = v;
            if (emit) {
                const float f[4] = {v.x, v.y, v.z, v.w};
                #pragma unroll
                for (int j = 0; j < 4; j++) {
                    const __half h = __float2half(f[j]);
                    sh[t4 * 4 + j][ci] = h;
                    sl[t4 * 4 + j][ci] = __float2half(f[j] - __half2float(h));
                }
            }
        }
        __syncthreads();
        if (emit) {
            for (int idx = tid; idx < 1024; idx += 256) {
                const int arr = idx >> 9;
                const int rem = idx & 511;
                const int r = rem >> 2, q = rem & 3;
                const __half* src = arr ? &sl[r][q * 8] : &sh[r][q * 8];
                uint16_t tmp[8];
                #pragma unroll
                for (int j = 0; j < 8; j++) tmp[j] = ((const uint16_t*)src)[j];
                __half* dst = (arr ? g_lo : g_hi) + ((size_t)b * TLEN + ts + r) * CPAD + c0 + q * 8;
                *(uint4*)dst = *(const uint4*)tmp;
            }
        }
        __syncthreads();
    }
}

// ================= launch =================
extern "C" void kernel_launch(void* const* d_in, const int* in_sizes, int n_in,
                              void* d_out, int out_size)
{
    const float* X    = (const float*)d_in[0];
    const int*   subj = (const int*)  d_in[1];
    const float* w0   = (const float*)d_in[2];
    const float* b0   = (const float*)d_in[3];
    const float* w1   = (const float*)d_in[4];
    const float* b1   = (const float*)d_in[5];
    const float* w2   = (const float*)d_in[6];
    const float* b2   = (const float*)d_in[7];
    const float* g0   = (const float*)d_in[8];
    const float* be0  = (const float*)d_in[9];
    const float* g1   = (const float*)d_in[10];
    const float* be1  = (const float*)d_in[11];
    const float* g2   = (const float*)d_in[12];
    const float* be2  = (const float*)d_in[13];
    float* out = (float*)d_out;

    float* bufA; cudaGetSymbolAddress((void**)&bufA, g_bufA);
    float* bufB; cudaGetSymbolAddress((void**)&bufB, g_bufB);
    __half* xhi; cudaGetSymbolAddress((void**)&xhi, g_hi);
    __half* xlo; cudaGetSymbolAddress((void**)&xlo, g_lo);
    __half* wf;  cudaGetSymbolAddress((void**)&wf,  g_wfmt);
    const size_t wstep = (size_t)3 * 320 * 320;

    cudaFuncSetAttribute(conv_mma_kernel,
                         cudaFuncAttributeMaxDynamicSharedMemorySize, CONV_SMEM);

    const dim3 cgrid(5, 4, BATCH);     // 64-co tiles x 128-t tiles x batch
    const dim3 egrid(10, BATCH);
    const int wfmt_n = 3 * 320 * 320;

    // ---- prologue (conv layer-0 kept at launch index 3 for ncu) ----
    wfmt_kernel<<<(wfmt_n + 255) / 256, 256>>>(w0, 271, 0);      // 0
    convert_x_tr_kernel<<<egrid, 256>>>(X, 271);                 // 1
    wfmt_kernel<<<(wfmt_n + 255) / 256, 256>>>(w1, COUT, 1);     // 2

    // ---- layer 0 (272 ci padded -> 9 chunks of 32) ----
    conv_mma_kernel<<<cgrid, 256, CONV_SMEM>>>(xhi, xlo, wf, b0, nullptr, bufA, 9);   // 3
    stats_reduce_g<<<NSUBJ * COUT, 128>>>(subj, g0, be0);
    bn_gelu_tr_kernel<<<egrid, 256>>>(bufA, subj, 1);
    wfmt_kernel<<<(wfmt_n + 255) / 256, 256>>>(w2, COUT, 2);

    // ---- layer 1 ----
    conv_mma_kernel<<<cgrid, 256, CONV_SMEM>>>(xhi, xlo, wf + wstep, b1, bufA, bufB, 10);
    stats_reduce_g<<<NSUBJ * COUT, 128>>>(subj, g1, be1);
    bn_gelu_tr_kernel<<<egrid, 256>>>(bufB, subj, 1);

    // ---- layer 2 ----
    conv_mma_kernel<<<cgrid, 256, CONV_SMEM>>>(xhi, xlo, wf + 2 * wstep, b2, bufB, out, 10);
    stats_reduce_g<<<NSUBJ * COUT, 128>>>(subj, g2, be2);
    bn_gelu_tr_kernel<<<egrid, 256>>>(out, subj, 0);
}

// round 16
// speedup vs baseline: 1.6506x; 1.0398x over previous
#include <cuda_runtime.h>
#include <cuda_fp16.h>
#include <cstdint>
#include <math.h>

#define BATCH 256
#define TLEN  512
#define COUT  320
#define CPAD  320
#define NSUBJ 4
#define EPSBN 1e-5f

// ================= scratch (no allocations allowed) =================
__device__ float g_bufA[(size_t)BATCH * COUT * TLEN];
__device__ float g_bufB[(size_t)BATCH * COUT * TLEN];
__device__ __half g_hi[(size_t)BATCH * TLEN * CPAD];   // [b][t][c] fp16 activations
__device__ __half g_wfmt[3 * 3 * 320 * 320];           // [layer][ko][co][ci] fp16 weights
__device__ float g_part1[8 * BATCH * COUT];            // [tt][b][co]
__device__ float g_part2[8 * BATCH * COUT];
__device__ float g_scale[NSUBJ * COUT];
__device__ float g_shift[NSUBJ * COUT];

// ================= mma / ldmatrix / cp.async helpers =================
__device__ __forceinline__ uint32_t smem_addr(const void* p) {
    return (uint32_t)__cvta_generic_to_shared(p);
}
__device__ __forceinline__ void ldsm_x4(uint32_t* r, uint32_t addr) {
    asm volatile("ldmatrix.sync.aligned.m8n8.x4.shared.b16 {%0,%1,%2,%3}, [%4];"
                 : "=r"(r[0]), "=r"(r[1]), "=r"(r[2]), "=r"(r[3]) : "r"(addr));
}
__device__ __forceinline__ void ldsm_x2(uint32_t* r, uint32_t addr) {
    asm volatile("ldmatrix.sync.aligned.m8n8.x2.shared.b16 {%0,%1}, [%2];"
                 : "=r"(r[0]), "=r"(r[1]) : "r"(addr));
}
__device__ __forceinline__ void mma_f32(float* c, const uint32_t* a, const uint32_t* b) {
    asm volatile("mma.sync.aligned.m16n8k16.row.col.f32.f16.f16.f32 "
                 "{%0,%1,%2,%3}, {%4,%5,%6,%7}, {%8,%9}, {%0,%1,%2,%3};"
                 : "+f"(c[0]), "+f"(c[1]), "+f"(c[2]), "+f"(c[3])
                 : "r"(a[0]), "r"(a[1]), "r"(a[2]), "r"(a[3]), "r"(b[0]), "r"(b[1]));
}
__device__ __forceinline__ void cp16(uint32_t dst, const void* src) {
    asm volatile("cp.async.cg.shared.global [%0], [%1], 16;" :: "r"(dst), "l"(src));
}
__device__ __forceinline__ void cp16z(uint32_t dst, const void* src, int sz) {
    asm volatile("cp.async.cg.shared.global [%0], [%1], 16, %2;" :: "r"(dst), "l"(src), "r"(sz));
}
#define CP_COMMIT() asm volatile("cp.async.commit_group;")
#define CP_WAIT(n)  asm volatile("cp.async.wait_group %0;" :: "n"(n))

// 64B-row swizzle: 16B-half selector, conflict-free ldsm 8-row phases
#define SWH2(r, h) ((h) ^ ((r) & 3) ^ (((r) >> 2) & 1))

// ================= conv via warp MMA, K=32 stages, pure fp16 =================
// CTA tile: 128 t x 64 co; 8 warps (4 t x 2 co); warp tile 32t x 32co.
// A = X^T smem [row=t][32 ci] (tap = +ko rows), B = W smem [co][32 ci].
// Single product f32acc x*W (both fp16-rounded); rel_err ~5e-4 < 1e-3.
#define XROWS   132
#define XSTG    (XROWS * 64)             // 8448 B per stage
#define WTILE   (64 * 64)                // 4096 B per ko tile
#define WSTG    (3 * WTILE)              // 12288 B per stage
#define WBASE   (2 * XSTG)               // 16896
#define CONV_SMEM (WBASE + 2 * WSTG)     // 41472 B

__global__ __launch_bounds__(256, 3)
void conv_mma_kernel(const __half* __restrict__ xin,
                     const __half* __restrict__ wf,
                     const float* __restrict__ bias,
                     const float* __restrict__ resid,
                     float* __restrict__ out,
                     int nch)
{
    extern __shared__ char smem[];
    const uint32_t sb = smem_addr(smem);

    const int tid  = threadIdx.x;
    const int wid  = tid >> 5;
    const int lane = tid & 31;
    const int co_blk = blockIdx.x * 64;
    const int t0     = blockIdx.y * 128;
    const int b      = blockIdx.z;

    const int warp_t0  = (wid >> 1) * 32;      // 0,32,64,96
    const int warp_co0 = (wid & 1) * 32;       // 0,32

    float acc[2][4][4];
    #pragma unroll
    for (int m = 0; m < 2; m++)
        #pragma unroll
        for (int n = 0; n < 4; n++)
            #pragma unroll
            for (int k = 0; k < 4; k++) acc[m][n][k] = 0.f;

    const int a_row = lane & 15, a_h = lane >> 4;
    const int b_row = lane & 7,  b_h = (lane >> 3) & 1;
    const int lrow = tid >> 2, lh = tid & 3;

    auto load_chunk = [&](int ch, int st) {
        const int c0 = ch * 32;
        // X: 130 rows x 4 halves
        #pragma unroll
        for (int pass = 0; pass < 3; pass++) {
            const int row = pass * 64 + lrow;
            if (row < 130) {
                const int t  = t0 - 1 + row;
                const int tc = t < 0 ? 0 : (t > TLEN - 1 ? TLEN - 1 : t);
                const __half* src = xin + ((size_t)b * TLEN + tc) * CPAD + c0 + lh * 8;
                const uint32_t dst = sb + st * XSTG + row * 64 + SWH2(row, lh) * 16;
                cp16z(dst, src, (t >= 0 && t < TLEN) ? 16 : 0);
            }
        }
        // W: 3 ko tiles x 64 co x 4 halves
        #pragma unroll
        for (int tile = 0; tile < 3; tile++) {
            const __half* src = wf + ((size_t)tile * 320 + co_blk + lrow) * 320 + c0 + lh * 8;
            const uint32_t dst = sb + WBASE + st * WSTG + tile * WTILE + lrow * 64 + SWH2(lrow, lh) * 16;
            cp16(dst, src);
        }
        CP_COMMIT();
    };

    load_chunk(0, 0);

    for (int ch = 0; ch < nch; ch++) {
        const int st = ch & 1;
        if (ch + 1 < nch) { load_chunk(ch + 1, st ^ 1); CP_WAIT(1); }
        else              { CP_WAIT(0); }
        __syncthreads();

        const uint32_t xb = sb + st * XSTG;
        const uint32_t wb = sb + WBASE + st * WSTG;

        #pragma unroll
        for (int kk = 0; kk < 2; kk++) {
            #pragma unroll
            for (int ko = 0; ko < 3; ko++) {
                uint32_t bh[4][2];
                #pragma unroll
                for (int n = 0; n < 4; n++) {
                    const int wr = warp_co0 + n * 8 + b_row;
                    const int hh = kk * 2 + b_h;
                    ldsm_x2(bh[n], wb + ko * WTILE + (uint32_t)(wr * 64 + SWH2(wr, hh) * 16));
                }
                uint32_t a[2][4];
                #pragma unroll
                for (int m = 0; m < 2; m++) {
                    const int xr = warp_t0 + m * 16 + ko + a_row;
                    const int hh = kk * 2 + a_h;
                    ldsm_x4(a[m], xb + (uint32_t)(xr * 64 + SWH2(xr, hh) * 16));
                }
                #pragma unroll
                for (int m = 0; m < 2; m++)
                    #pragma unroll
                    for (int n = 0; n < 4; n++) mma_f32(acc[m][n], a[m], bh[n]);
            }
        }
        __syncthreads();
    }

    // ---- epilogue: two 64-t halves via smem transpose; fused BN partial stats ----
    float* sO = (float*)smem;                   // [64 co][68 t] = 17408 B
    #pragma unroll
    for (int th = 0; th < 2; th++) {
        if ((warp_t0 >> 6) == th) {
            const int tb2 = warp_t0 & 63;       // 0 or 32
            const int t_l = lane >> 2;
            #pragma unroll
            for (int n = 0; n < 4; n++) {
                const int co_l = warp_co0 + n * 8 + ((lane & 3) << 1);
                #pragma unroll
                for (int m = 0; m < 2; m++) {
                    const int t = tb2 + m * 16 + t_l;
                    sO[co_l * 68 + t]           = acc[m][n][0];
                    sO[(co_l + 1) * 68 + t]     = acc[m][n][1];
                    sO[co_l * 68 + t + 8]       = acc[m][n][2];
                    sO[(co_l + 1) * 68 + t + 8] = acc[m][n][3];
                }
            }
        }
        __syncthreads();

        const int tt = blockIdx.y * 2 + th;
        for (int idx = tid; idx < 64 * 16; idx += 256) {
            const int co = idx >> 4, t4 = idx & 15;
            float4 v = *(const float4*)&sO[co * 68 + t4 * 4];
            const float bv = bias[co_blk + co];
            v.x += bv; v.y += bv; v.z += bv; v.w += bv;
            const size_t adr = ((size_t)b * COUT + co_blk + co) * TLEN + t0 + th * 64 + t4 * 4;
            if (resid) {
                const float4 r = *(const float4*)&resid[adr];
                v.x += r.x; v.y += r.y; v.z += r.z; v.w += r.w;
            }
            *(float4*)&out[adr] = v;
            float s = v.x + v.y + v.z + v.w;
            float q = v.x * v.x + v.y * v.y + v.z * v.z + v.w * v.w;
            #pragma unroll
            for (int o = 8; o > 0; o >>= 1) {
                s += __shfl_down_sync(0xffffffffu, s, o, 16);
                q += __shfl_down_sync(0xffffffffu, q, o, 16);
            }
            if ((lane & 15) == 0) {
                const size_t pa = ((size_t)tt * BATCH + b) * COUT + co_blk + co;
                g_part1[pa] = s;
                g_part2[pa] = q;
            }
        }
        __syncthreads();
    }
}

// ================= weight reformat: [ko][co320][ci320] fp16 =================
__global__ void wfmt_kernel(const float* __restrict__ W, int Cin, int layer)
{
    const int idx = blockIdx.x * blockDim.x + threadIdx.x;
    if (idx >= 3 * 320 * 320) return;
    const int ci = idx % 320;
    const int co = (idx / 320) % 320;
    const int ko = idx / (320 * 320);
    float v = 0.f;
    if (ci < Cin) v = W[((size_t)co * Cin + ci) * 3 + ko];
    g_wfmt[(size_t)layer * 3 * 320 * 320 + idx] = __float2half(v);
}

// ================= input convert: X fp32 [b][Cin][512] -> fp16 [b][t][320] =================
__global__ void convert_x_tr_kernel(const float* __restrict__ x, int Cin)
{
    __shared__ __half sh[128][33];
    const int tid = threadIdx.x;
    const int b   = blockIdx.y;
    const int c0  = blockIdx.x * 32;

    for (int ts = 0; ts < TLEN; ts += 128) {
        for (int idx = tid; idx < 1024; idx += 256) {
            const int ci = idx >> 5, t4 = idx & 31;
            const int c = c0 + ci;
            float4 v = make_float4(0.f, 0.f, 0.f, 0.f);
            if (c < Cin) v = *(const float4*)&x[((size_t)b * Cin + c) * TLEN + ts + t4 * 4];
            const float f[4] = {v.x, v.y, v.z, v.w};
            #pragma unroll
            for (int j = 0; j < 4; j++) sh[t4 * 4 + j][ci] = __float2half(f[j]);
        }
        __syncthreads();
        for (int idx = tid; idx < 512; idx += 256) {
            const int r = idx >> 2, q = idx & 3;
            const __half* src = &sh[r][q * 8];
            uint16_t tmp[8];
            #pragma unroll
            for (int j = 0; j < 8; j++) tmp[j] = ((const uint16_t*)src)[j];
            __half* dst = g_hi + ((size_t)b * TLEN + ts + r) * CPAD + c0 + q * 8;
            *(uint4*)dst = *(const uint4*)tmp;
        }
        __syncthreads();
    }
}

// ====== BN stats reduce: one block per (s,c), deterministic tree ======
__global__ __launch_bounds__(128)
void stats_reduce_g(const int* __restrict__ subj,
                    const float* __restrict__ gamma, const float* __restrict__ beta)
{
    __shared__ float ss[128], sq[128];
    __shared__ int   sn[128];
    const int bid = blockIdx.x;            // s*COUT + c
    const int c   = bid % COUT;
    const int s   = bid / COUT;
    const int tid = threadIdx.x;

    float sum = 0.f, q = 0.f;
    int nb = 0;
    #pragma unroll
    for (int half = 0; half < 2; half++) {
        const int b = half * 128 + tid;
        if (subj[b] == s) {
            nb++;
            #pragma unroll
            for (int tt = 0; tt < 8; tt++) {
                const size_t pa = ((size_t)tt * BATCH + b) * COUT + c;
                sum += g_part1[pa];
                q   += g_part2[pa];
            }
        }
    }
    ss[tid] = sum; sq[tid] = q; sn[tid] = nb;
    __syncthreads();
    #pragma unroll
    for (int o = 64; o > 0; o >>= 1) {
        if (tid < o) {
            ss[tid] += ss[tid + o];
            sq[tid] += sq[tid + o];
            sn[tid] += sn[tid + o];
        }
        __syncthreads();
    }
    if (tid == 0) {
        const float cnt  = fmaxf((float)sn[0] * (float)TLEN, 1.0f);
        const float mean = ss[0] / cnt;
        const float var  = sq[0] / cnt - mean * mean;
        const float sc   = gamma[bid] * rsqrtf(var + EPSBN);
        g_scale[bid] = sc;
        g_shift[bid] = beta[bid] - mean * sc;
    }
}

// ====== BN apply + exact GELU (in place) + transposed fp16 emit ======
__device__ __forceinline__ float gelu_exact(float y) {
    return 0.5f * y * (1.0f + erff(y * 0.70710678118654752440f));
}

__global__ void bn_gelu_tr_kernel(float* __restrict__ x, const int* __restrict__ subj, int emit)
{
    __shared__ __half sh[128][33];
    const int tid = threadIdx.x;
    const int b   = blockIdx.y;
    const int c0  = blockIdx.x * 32;
    const int s   = subj[b];

    for (int ts = 0; ts < TLEN; ts += 128) {
        for (int idx = tid; idx < 1024; idx += 256) {
            const int ci = idx >> 5, t4 = idx & 31;
            const int c = c0 + ci;
            const float sc = g_scale[s * COUT + c];
            const float sv = g_shift[s * COUT + c];
            float* xp = &x[((size_t)b * COUT + c) * TLEN + ts + t4 * 4];
            float4 v = *(const float4*)xp;
            v.x = gelu_exact(v.x * sc + sv);
            v.y = gelu_exact(v.y * sc + sv);
            v.z = gelu_exact(v.z * sc + sv);
            v.w = gelu_exact(v.w * sc + sv);
            *(float4*)xp = v;
            if (emit) {
                const float f[4] = {v.x, v.y, v.z, v.w};
                #pragma unroll
                for (int j = 0; j < 4; j++) sh[t4 * 4 + j][ci] = __float2half(f[j]);
            }
        }
        __syncthreads();
        if (emit) {
            for (int idx = tid; idx < 512; idx += 256) {
                const int r = idx >> 2, q = idx & 3;
                const __half* src = &sh[r][q * 8];
                uint16_t tmp[8];
                #pragma unroll
                for (int j = 0; j < 8; j++) tmp[j] = ((const uint16_t*)src)[j];
                __half* dst = g_hi + ((size_t)b * TLEN + ts + r) * CPAD + c0 + q * 8;
                *(uint4*)dst = *(const uint4*)tmp;
            }
        }
        __syncthreads();
    }
}

// ================= launch =================
extern "C" void kernel_launch(void* const* d_in, const int* in_sizes, int n_in,
                              void* d_out, int out_size)
{
    const float* X    = (const float*)d_in[0];
    const int*   subj = (const int*)  d_in[1];
    const float* w0   = (const float*)d_in[2];
    const float* b0   = (const float*)d_in[3];
    const float* w1   = (const float*)d_in[4];
    const float* b1   = (const float*)d_in[5];
    const float* w2   = (const float*)d_in[6];
    const float* b2   = (const float*)d_in[7];
    const float* g0   = (const float*)d_in[8];
    const float* be0  = (const float*)d_in[9];
    const float* g1   = (const float*)d_in[10];
    const float* be1  = (const float*)d_in[11];
    const float* g2   = (const float*)d_in[12];
    const float* be2  = (const float*)d_in[13];
    float* out = (float*)d_out;

    float* bufA; cudaGetSymbolAddress((void**)&bufA, g_bufA);
    float* bufB; cudaGetSymbolAddress((void**)&bufB, g_bufB);
    __half* xin; cudaGetSymbolAddress((void**)&xin, g_hi);
    __half* wf;  cudaGetSymbolAddress((void**)&wf,  g_wfmt);
    const size_t wstep = (size_t)3 * 320 * 320;

    cudaFuncSetAttribute(conv_mma_kernel,
                         cudaFuncAttributeMaxDynamicSharedMemorySize, CONV_SMEM);

    const dim3 cgrid(5, 4, BATCH);     // 64-co tiles x 128-t tiles x batch
    const dim3 egrid(10, BATCH);
    const int wfmt_n = 3 * 320 * 320;

    // ---- prologue (conv layer-0 kept at launch index 3 for ncu) ----
    wfmt_kernel<<<(wfmt_n + 255) / 256, 256>>>(w0, 271, 0);      // 0
    convert_x_tr_kernel<<<egrid, 256>>>(X, 271);                 // 1
    wfmt_kernel<<<(wfmt_n + 255) / 256, 256>>>(w1, COUT, 1);     // 2

    // ---- layer 0 (272 ci padded -> 9 chunks of 32) ----
    conv_mma_kernel<<<cgrid, 256, CONV_SMEM>>>(xin, wf, b0, nullptr, bufA, 9);   // 3
    stats_reduce_g<<<NSUBJ * COUT, 128>>>(subj, g0, be0);
    bn_gelu_tr_kernel<<<egrid, 256>>>(bufA, subj, 1);
    wfmt_kernel<<<(wfmt_n + 255) / 256, 256>>>(w2, COUT, 2);

    // ---- layer 1 ----
    conv_mma_kernel<<<cgrid, 256, CONV_SMEM>>>(xin, wf + wstep, b1, bufA, bufB, 10);
    stats_reduce_g<<<NSUBJ * COUT, 128>>>(subj, g1, be1);
    bn_gelu_tr_kernel<<<egrid, 256>>>(bufB, subj, 1);

    // ---- layer 2 ----
    conv_mma_kernel<<<cgrid, 256, CONV_SMEM>>>(xin, wf + 2 * wstep, b2, bufB, out, 10);
    stats_reduce_g<<<NSUBJ * COUT, 128>>>(subj, g2, be2);
    bn_gelu_tr_kernel<<<egrid, 256>>>(out, subj, 0);
}